// round 2
// baseline (speedup 1.0000x reference)
#include <cuda_runtime.h>

#define NN 50000
#define EE 400000
#define HC 128
#define EPS_SKIP_F 1.000001f

// ---------------- scratch (static device allocations) ----------------
__device__ float g_xm[2][NN * HC];      // per-branch transformed features
__device__ float g_ssrc[2][NN * 4];     // per-node per-head src logit part
__device__ float g_sdst[2][NN * 4];     // per-node per-head dst logit part
__device__ float g_denom[2][NN * 4];    // softmax denominators
__device__ int   g_deg[2 * NN];         // in-degree per (branch,node)
__device__ int   g_off[2 * NN];         // CSR offsets (exclusive prefix of deg)
__device__ int   g_cur[2 * NN];         // scatter cursors
__device__ int   g_psrc[2 * EE];        // target-sorted source indices
__device__ float4 g_pw[2 * EE];         // target-sorted per-head weights

// ---------------- kernels ----------------

__global__ void zero_kernel() {
    int i = blockIdx.x * blockDim.x + threadIdx.x;
    if (i < 2 * NN * 4) ((float*)g_denom)[i] = 0.0f;
    if (i < 2 * NN) g_deg[i] = 0;
}

// Fused triple GEMM: y = x @ W for W in {W_low, W_up, W_skip}.
// blockIdx.y selects which. BM=128, BN=128(full), BK=32.
__global__ __launch_bounds__(256, 2) void gemm_kernel(
    const float* __restrict__ x,
    const float* __restrict__ Wl,
    const float* __restrict__ Wu,
    const float* __restrict__ Ws,
    float* __restrict__ out_skip)
{
    __shared__ float As[32][132];   // transposed x tile: As[k][m]; pad 132 keeps rows 16B-aligned
    __shared__ float Bs[32][128];   // W tile: Bs[k][n]

    const int by = blockIdx.y;
    const float* __restrict__ W = (by == 0) ? Wl : ((by == 1) ? Wu : Ws);
    float* __restrict__ out = (by == 0) ? g_xm[0] : ((by == 1) ? g_xm[1] : out_skip);

    const int bm0 = blockIdx.x * 128;
    const int t = threadIdx.x;
    const int tx = t & 15;
    const int ty = t >> 4;

    float acc[8][8];
#pragma unroll
    for (int i = 0; i < 8; i++)
#pragma unroll
        for (int j = 0; j < 8; j++) acc[i][j] = 0.0f;

    for (int k0 = 0; k0 < 128; k0 += 32) {
        // load x tile (128 rows x 32 cols), store transposed
        {
            const int col4 = t & 7;    // k-offset/4
            const int rowb = t >> 3;   // 0..31
#pragma unroll
            for (int i = 0; i < 4; i++) {
                const int row = rowb + 32 * i;
                const int m = bm0 + row;
                float4 v = make_float4(0.f, 0.f, 0.f, 0.f);
                if (m < NN) v = *(const float4*)&x[m * 128 + k0 + col4 * 4];
                As[col4 * 4 + 0][row] = v.x;
                As[col4 * 4 + 1][row] = v.y;
                As[col4 * 4 + 2][row] = v.z;
                As[col4 * 4 + 3][row] = v.w;
            }
        }
        // load W tile (32 rows x 128 cols)
        {
            const int n4 = t & 31;   // n/4
            const int kk = t >> 5;   // 0..7
#pragma unroll
            for (int i = 0; i < 4; i++) {
                const int k = kk + 8 * i;
                float4 v = *(const float4*)&W[(k0 + k) * 128 + n4 * 4];
                *(float4*)&Bs[k][n4 * 4] = v;
            }
        }
        __syncthreads();

#pragma unroll
        for (int k = 0; k < 32; k++) {
            float4 a0 = *(float4*)&As[k][ty * 8];
            float4 a1 = *(float4*)&As[k][ty * 8 + 4];
            float4 b0 = *(float4*)&Bs[k][tx * 8];
            float4 b1 = *(float4*)&Bs[k][tx * 8 + 4];
            float a[8] = {a0.x, a0.y, a0.z, a0.w, a1.x, a1.y, a1.z, a1.w};
            float b[8] = {b0.x, b0.y, b0.z, b0.w, b1.x, b1.y, b1.z, b1.w};
#pragma unroll
            for (int i = 0; i < 8; i++)
#pragma unroll
                for (int j = 0; j < 8; j++) acc[i][j] += a[i] * b[j];
        }
        __syncthreads();
    }

    const float scale = (by == 2) ? EPS_SKIP_F : 1.0f;
#pragma unroll
    for (int i = 0; i < 8; i++) {
        const int m = bm0 + ty * 8 + i;
        if (m < NN) {
#pragma unroll
            for (int j = 0; j < 8; j += 4) {
                float4 v = make_float4(acc[i][j + 0] * scale,
                                       acc[i][j + 1] * scale,
                                       acc[i][j + 2] * scale,
                                       acc[i][j + 3] * scale);
                *(float4*)&out[m * 128 + tx * 8 + j] = v;
            }
        }
    }
}

// Per-node per-head attention logit parts: s = xm[n,h,:] . a[h,:]
__global__ void s_kernel(const float* __restrict__ asl, const float* __restrict__ adl,
                         const float* __restrict__ asu, const float* __restrict__ adu)
{
    int idx = blockIdx.x * blockDim.x + threadIdx.x;
    if (idx >= 2 * NN * 4) return;
    const int branch = idx / (NN * 4);
    const int r = idx - branch * (NN * 4);
    const int n = r >> 2;
    const int h = r & 3;
    const float* __restrict__ xm = g_xm[branch];
    const float* __restrict__ asrc = branch ? asu : asl;
    const float* __restrict__ adst = branch ? adu : adl;
    const float* __restrict__ xr = &xm[n * 128 + h * 32];
    float ss = 0.f, sd = 0.f;
#pragma unroll
    for (int i = 0; i < 32; i++) {
        float v = xr[i];
        ss += v * asrc[h * 32 + i];
        sd += v * adst[h * 32 + i];
    }
    g_ssrc[branch][r] = ss;
    g_sdst[branch][r] = sd;
}

__device__ __forceinline__ float lrelu_exp(float a) {
    a = (a > 0.f) ? a : 0.01f * a;
    return __expf(a);
}

// Pass 1: per edge, exp(leaky_relu(logit)) for all 4 heads; accumulate softmax
// denominator at the target node and count the target's in-degree.
__global__ void pass1_kernel(const int* __restrict__ t0, const int* __restrict__ s0,
                             const int* __restrict__ t1, const int* __restrict__ s1)
{
    int idx = blockIdx.x * blockDim.x + threadIdx.x;
    if (idx >= 2 * EE) return;
    const int branch = (idx >= EE) ? 1 : 0;
    const int e = idx - branch * EE;
    const int tgt = (branch ? t1 : t0)[e];
    const int src = (branch ? s1 : s0)[e];
    float4 ss = *(const float4*)&g_ssrc[branch][src * 4];
    float4 sd = *(const float4*)&g_sdst[branch][tgt * 4];
    float ex = lrelu_exp(ss.x + sd.x);
    float ey = lrelu_exp(ss.y + sd.y);
    float ez = lrelu_exp(ss.z + sd.z);
    float ew = lrelu_exp(ss.w + sd.w);
    float* p = &g_denom[branch][tgt * 4];
    asm volatile("red.global.add.v4.f32 [%0], {%1,%2,%3,%4};"
                 :: "l"(p), "f"(ex), "f"(ey), "f"(ez), "f"(ew) : "memory");
    atomicAdd(&g_deg[branch * NN + tgt], 1);
}

// Single-block exclusive prefix scan over the 2*NN degree array.
__global__ void scan_kernel() {
    __shared__ int sums[1024];
    const int T = 1024;
    const int per = (2 * NN + T - 1) / T;   // 98
    const int t = threadIdx.x;
    const int start = t * per;
    const int end = min(start + per, 2 * NN);
    int s = 0;
    for (int i = start; i < end; i++) s += g_deg[i];
    sums[t] = s;
    __syncthreads();
    // Hillis-Steele inclusive scan
    for (int d = 1; d < T; d <<= 1) {
        int v = (t >= d) ? sums[t - d] : 0;
        __syncthreads();
        sums[t] += v;
        __syncthreads();
    }
    int run = (t == 0) ? 0 : sums[t - 1];
    for (int i = start; i < end; i++) {
        int d = g_deg[i];
        g_off[i] = run;
        g_cur[i] = run;
        run += d;
    }
}

// Scatter edges into target-sorted order, storing source index and the
// normalized per-head weight (e / (denom + 1e-16)).
__global__ void scatter_kernel(const int* __restrict__ t0, const int* __restrict__ s0,
                               const int* __restrict__ t1, const int* __restrict__ s1)
{
    int idx = blockIdx.x * blockDim.x + threadIdx.x;
    if (idx >= 2 * EE) return;
    const int branch = (idx >= EE) ? 1 : 0;
    const int e = idx - branch * EE;
    const int tgt = (branch ? t1 : t0)[e];
    const int src = (branch ? s1 : s0)[e];
    float4 ss = *(const float4*)&g_ssrc[branch][src * 4];
    float4 sd = *(const float4*)&g_sdst[branch][tgt * 4];
    float4 dn = *(const float4*)&g_denom[branch][tgt * 4];
    float4 w;
    w.x = lrelu_exp(ss.x + sd.x) / (dn.x + 1e-16f);
    w.y = lrelu_exp(ss.y + sd.y) / (dn.y + 1e-16f);
    w.z = lrelu_exp(ss.z + sd.z) / (dn.z + 1e-16f);
    w.w = lrelu_exp(ss.w + sd.w) / (dn.w + 1e-16f);
    int pos = atomicAdd(&g_cur[branch * NN + tgt], 1);
    g_psrc[pos] = src;
    g_pw[pos] = w;
}

// One warp per node: accumulate weighted messages from both branches in
// registers, add the (pre-written) skip term, relu, write once.
__global__ __launch_bounds__(256) void agg_kernel(float* __restrict__ out)
{
    const int gw = (blockIdx.x * blockDim.x + threadIdx.x) >> 5;
    if (gw >= NN) return;
    const int n = gw;
    const int lane = threadIdx.x & 31;
    const int h = lane >> 3;

    float4 acc = make_float4(0.f, 0.f, 0.f, 0.f);
#pragma unroll
    for (int b = 0; b < 2; b++) {
        const int base = b * NN + n;
        const int off = g_off[base];
        const int deg = g_deg[base];
        const float* __restrict__ xm = g_xm[b];
        for (int j = 0; j < deg; j++) {
            const int s = __ldg(&g_psrc[off + j]);           // broadcast
            const float wh = __ldg(&((const float*)&g_pw[off + j])[h]);
            const float4 v = *(const float4*)&xm[s * 128 + lane * 4];
            acc.x += wh * v.x;
            acc.y += wh * v.y;
            acc.z += wh * v.z;
            acc.w += wh * v.w;
        }
    }
    float4* po = (float4*)&out[n * 128 + lane * 4];
    float4 o = *po;   // skip term (already scaled by EPS)
    o.x = fmaxf(o.x + acc.x, 0.f);
    o.y = fmaxf(o.y + acc.y, 0.f);
    o.z = fmaxf(o.z + acc.z, 0.f);
    o.w = fmaxf(o.w + acc.w, 0.f);
    *po = o;
}

// ---------------- launch ----------------
extern "C" void kernel_launch(void* const* d_in, const int* in_sizes, int n_in,
                              void* d_out, int out_size)
{
    const float* x      = (const float*)d_in[0];
    const float* W_low  = (const float*)d_in[1];
    const float* a_sl   = (const float*)d_in[2];
    const float* a_dl   = (const float*)d_in[3];
    const float* W_up   = (const float*)d_in[4];
    const float* a_su   = (const float*)d_in[5];
    const float* a_du   = (const float*)d_in[6];
    const float* W_skip = (const float*)d_in[7];
    const int* lower_tgt = (const int*)d_in[8];
    const int* lower_src = (const int*)d_in[9];
    const int* upper_tgt = (const int*)d_in[10];
    const int* upper_src = (const int*)d_in[11];
    float* out = (float*)d_out;

    // 1. zero denominators + degree counters
    zero_kernel<<<(2 * NN * 4 + 255) / 256, 256>>>();

    // 2. fused triple GEMM (writes skip*EPS into out)
    dim3 ggrid((NN + 127) / 128, 3);
    gemm_kernel<<<ggrid, 256>>>(x, W_low, W_up, W_skip, out);

    // 3. per-node logit parts
    s_kernel<<<(2 * NN * 4 + 255) / 256, 256>>>(a_sl, a_dl, a_su, a_du);

    // 4. softmax denominators + degree histogram
    pass1_kernel<<<(2 * EE + 255) / 256, 256>>>(lower_tgt, lower_src, upper_tgt, upper_src);

    // 5. CSR offsets
    scan_kernel<<<1, 1024>>>();

    // 6. scatter edges (src + normalized weights) into target-sorted order
    scatter_kernel<<<(2 * EE + 255) / 256, 256>>>(lower_tgt, lower_src, upper_tgt, upper_src);

    // 7. warp-per-node aggregation + skip + relu (single write, no atomics)
    {
        long long threads = (long long)NN * 32;
        int blocks = (int)((threads + 255) / 256);
        agg_kernel<<<blocks, 256>>>(out);
    }
}

// round 4
// speedup vs baseline: 1.3692x; 1.3692x over previous
#include <cuda_runtime.h>
#include <cstdint>

#define NN 50000
#define EE 400000
#define EPS_SKIP_F 1.000001f

// ---------------- scratch ----------------
__device__ float g_xm[2][NN * 128];   // per-branch transformed features
__device__ float g_ssrc[2][NN * 4];
__device__ float g_sdst[2][NN * 4];
__device__ float g_denom[2][NN * 4];
__device__ float g_ebuf[2][EE * 4];
__device__ float g_Wt[3][128 * 128];  // W^T as [n][k], fp32

// ---------------- helpers ----------------
__device__ __forceinline__ void split_tf32(float v, uint32_t& hi, uint32_t& lo) {
    uint32_t h;
    asm("cvt.rna.tf32.f32 %0, %1;" : "=r"(h) : "f"(v));
    float r = v - __uint_as_float(h);
    uint32_t l;
    asm("cvt.rna.tf32.f32 %0, %1;" : "=r"(l) : "f"(r));
    hi = h; lo = l;
}

__device__ __forceinline__ void mma_tf32(float* d,
                                         uint32_t a0, uint32_t a1, uint32_t a2, uint32_t a3,
                                         uint32_t b0, uint32_t b1) {
    asm volatile(
        "mma.sync.aligned.m16n8k8.row.col.f32.tf32.tf32.f32 "
        "{%0,%1,%2,%3}, {%4,%5,%6,%7}, {%8,%9}, {%0,%1,%2,%3};"
        : "+f"(d[0]), "+f"(d[1]), "+f"(d[2]), "+f"(d[3])
        : "r"(a0), "r"(a1), "r"(a2), "r"(a3), "r"(b0), "r"(b1));
}

// ---------------- prep: W -> W^T [n][k] ----------------
__global__ void prep_b_kernel(const float* __restrict__ Wl,
                              const float* __restrict__ Wu,
                              const float* __restrict__ Ws) {
    int i = blockIdx.x * blockDim.x + threadIdx.x;
    if (i >= 3 * 16384) return;
    const int b = i / 16384;
    const int r = i & 16383;
    const int k = r >> 7, n = r & 127;         // consecutive i -> consecutive n (coalesced read)
    const float* __restrict__ W = (b == 0) ? Wl : ((b == 1) ? Wu : Ws);
    g_Wt[b][n * 128 + k] = W[k * 128 + n];
}

// ---------------- mma.sync 3xTF32 GEMM: y = x @ W, 3 branches via blockIdx.y ----------------
#define PADK 132
#define GEMM_SMEM (2 * 128 * PADK * 4)

__global__ __launch_bounds__(256, 1) void gemm_mma_kernel(
    const float* __restrict__ x, float* __restrict__ out_skip)
{
    extern __shared__ float smem[];
    float* As = smem;                  // A[row][k], stride PADK
    float* Bs = smem + 128 * PADK;     // B[n][k],  stride PADK

    const int by = blockIdx.y;
    float* __restrict__ out = (by == 0) ? g_xm[0] : ((by == 1) ? g_xm[1] : out_skip);
    const int bm0 = blockIdx.x * 128;

    const int t = threadIdx.x;
    const int wid = t >> 5, lane = t & 31;
    const int lg = lane >> 2;          // group id 0..7
    const int lt = lane & 3;           // thread-in-group 0..3

    // ---- load A tile (x rows, fp32) ----
#pragma unroll
    for (int i = t; i < 4096; i += 256) {
        const int row = i >> 5;
        const int c4 = i & 31;
        const int m = bm0 + row;
        float4 v = make_float4(0.f, 0.f, 0.f, 0.f);
        if (m < NN) v = *(const float4*)&x[m * 128 + c4 * 4];
        *(float4*)&As[row * PADK + c4 * 4] = v;
    }
    // ---- load B tile (W^T rows, fp32) ----
    {
        const float* __restrict__ src = g_Wt[by];
#pragma unroll
        for (int i = t; i < 4096; i += 256) {
            const int n = i >> 5;
            const int c4 = i & 31;
            float4 v = *(const float4*)&src[n * 128 + c4 * 4];
            *(float4*)&Bs[n * PADK + c4 * 4] = v;
        }
    }
    __syncthreads();

    // warp tile: 32 rows x 64 cols
    const int wm = (wid & 3) * 32;
    const int wn = (wid >> 2) * 64;

    float acc[2][8][4];
#pragma unroll
    for (int mt = 0; mt < 2; mt++)
#pragma unroll
        for (int nt = 0; nt < 8; nt++)
#pragma unroll
            for (int c = 0; c < 4; c++) acc[mt][nt][c] = 0.f;

#pragma unroll
    for (int k0 = 0; k0 < 128; k0 += 8) {
        uint32_t ah[2][4], al[2][4];
#pragma unroll
        for (int mt = 0; mt < 2; mt++) {
            const int rb = wm + mt * 16 + lg;
            const float v0 = As[rb * PADK + k0 + lt];
            const float v1 = As[(rb + 8) * PADK + k0 + lt];
            const float v2 = As[rb * PADK + k0 + lt + 4];
            const float v3 = As[(rb + 8) * PADK + k0 + lt + 4];
            split_tf32(v0, ah[mt][0], al[mt][0]);
            split_tf32(v1, ah[mt][1], al[mt][1]);
            split_tf32(v2, ah[mt][2], al[mt][2]);
            split_tf32(v3, ah[mt][3], al[mt][3]);
        }
        uint32_t bh[8][2], bl[8][2];
#pragma unroll
        for (int nt = 0; nt < 8; nt++) {
            const int n = wn + nt * 8 + lg;
            const float v0 = Bs[n * PADK + k0 + lt];
            const float v1 = Bs[n * PADK + k0 + lt + 4];
            split_tf32(v0, bh[nt][0], bl[nt][0]);
            split_tf32(v1, bh[nt][1], bl[nt][1]);
        }
#pragma unroll
        for (int mt = 0; mt < 2; mt++)
#pragma unroll
            for (int nt = 0; nt < 8; nt++) {
                mma_tf32(acc[mt][nt], ah[mt][0], ah[mt][1], ah[mt][2], ah[mt][3],
                         bh[nt][0], bh[nt][1]);
                mma_tf32(acc[mt][nt], ah[mt][0], ah[mt][1], ah[mt][2], ah[mt][3],
                         bl[nt][0], bl[nt][1]);
                mma_tf32(acc[mt][nt], al[mt][0], al[mt][1], al[mt][2], al[mt][3],
                         bh[nt][0], bh[nt][1]);
            }
    }

    // ---- epilogue ----
    const float scale = (by == 2) ? EPS_SKIP_F : 1.0f;
#pragma unroll
    for (int mt = 0; mt < 2; mt++) {
        const int r0 = wm + mt * 16 + lg;
        const int m0 = bm0 + r0;
        const int m1 = m0 + 8;
#pragma unroll
        for (int nt = 0; nt < 8; nt++) {
            const int col = wn + nt * 8 + 2 * lt;
            if (m0 < NN) {
                float2 v = make_float2(acc[mt][nt][0] * scale, acc[mt][nt][1] * scale);
                *(float2*)&out[m0 * 128 + col] = v;
            }
            if (m1 < NN) {
                float2 v = make_float2(acc[mt][nt][2] * scale, acc[mt][nt][3] * scale);
                *(float2*)&out[m1 * 128 + col] = v;
            }
        }
    }
}

// ---------------- attention pipeline (R1-proven) ----------------
__global__ void zero_kernel() {
    int i = blockIdx.x * blockDim.x + threadIdx.x;
    if (i < 2 * NN * 4) ((float*)g_denom)[i] = 0.0f;
}

__global__ void s_kernel(const float* __restrict__ asl, const float* __restrict__ adl,
                         const float* __restrict__ asu, const float* __restrict__ adu)
{
    int idx = blockIdx.x * blockDim.x + threadIdx.x;
    if (idx >= 2 * NN * 4) return;
    const int branch = idx / (NN * 4);
    const int r = idx - branch * (NN * 4);
    const int n = r >> 2;
    const int h = r & 3;
    const float* __restrict__ xm = g_xm[branch];
    const float* __restrict__ asrc = branch ? asu : asl;
    const float* __restrict__ adst = branch ? adu : adl;
    const float* __restrict__ xr = &xm[n * 128 + h * 32];
    float ss = 0.f, sd = 0.f;
#pragma unroll
    for (int i = 0; i < 32; i++) {
        float v = xr[i];
        ss += v * asrc[h * 32 + i];
        sd += v * adst[h * 32 + i];
    }
    g_ssrc[branch][r] = ss;
    g_sdst[branch][r] = sd;
}

__device__ __forceinline__ float lrelu_exp(float a) {
    a = (a > 0.f) ? a : 0.01f * a;
    return __expf(a);
}

__global__ void pass1_kernel(const int* __restrict__ t0, const int* __restrict__ s0,
                             const int* __restrict__ t1, const int* __restrict__ s1)
{
    int idx = blockIdx.x * blockDim.x + threadIdx.x;
    if (idx >= 2 * EE) return;
    const int branch = (idx >= EE) ? 1 : 0;
    const int e = idx - branch * EE;
    const int tgt = (branch ? t1 : t0)[e];
    const int src = (branch ? s1 : s0)[e];
    float4 ss = *(const float4*)&g_ssrc[branch][src * 4];
    float4 sd = *(const float4*)&g_sdst[branch][tgt * 4];
    float ex = lrelu_exp(ss.x + sd.x);
    float ey = lrelu_exp(ss.y + sd.y);
    float ez = lrelu_exp(ss.z + sd.z);
    float ew = lrelu_exp(ss.w + sd.w);
    *(float4*)&g_ebuf[branch][e * 4] = make_float4(ex, ey, ez, ew);
    float* p = &g_denom[branch][tgt * 4];
    asm volatile("red.global.add.v4.f32 [%0], {%1,%2,%3,%4};"
                 :: "l"(p), "f"(ex), "f"(ey), "f"(ez), "f"(ew) : "memory");
}

__global__ void pass2_kernel(const int* __restrict__ t0, const int* __restrict__ s0,
                             const int* __restrict__ t1, const int* __restrict__ s1,
                             float* __restrict__ out)
{
    const int gw = (blockIdx.x * blockDim.x + threadIdx.x) >> 5;
    if (gw >= 2 * EE) return;
    const int lane = threadIdx.x & 31;
    const int branch = (gw >= EE) ? 1 : 0;
    const int e = gw - branch * EE;
    const int tgt = (branch ? t1 : t0)[e];
    const int src = (branch ? s1 : s0)[e];
    const int h = lane >> 3;
    const float eh = g_ebuf[branch][e * 4 + h];
    const float dh = g_denom[branch][tgt * 4 + h];
    const float w = eh / (dh + 1e-16f);
    const float4 v = *(const float4*)&g_xm[branch][src * 128 + lane * 4];
    float* p = &out[tgt * 128 + lane * 4];
    asm volatile("red.global.add.v4.f32 [%0], {%1,%2,%3,%4};"
                 :: "l"(p), "f"(v.x * w), "f"(v.y * w), "f"(v.z * w), "f"(v.w * w)
                 : "memory");
}

__global__ void relu_kernel(float* __restrict__ out) {
    int i = blockIdx.x * blockDim.x + threadIdx.x;
    if (i < NN * 32) {
        float4* p = (float4*)out + i;
        float4 v = *p;
        v.x = fmaxf(v.x, 0.f); v.y = fmaxf(v.y, 0.f);
        v.z = fmaxf(v.z, 0.f); v.w = fmaxf(v.w, 0.f);
        *p = v;
    }
}

// ---------------- launch ----------------
extern "C" void kernel_launch(void* const* d_in, const int* in_sizes, int n_in,
                              void* d_out, int out_size)
{
    const float* x      = (const float*)d_in[0];
    const float* W_low  = (const float*)d_in[1];
    const float* a_sl   = (const float*)d_in[2];
    const float* a_dl   = (const float*)d_in[3];
    const float* W_up   = (const float*)d_in[4];
    const float* a_su   = (const float*)d_in[5];
    const float* a_du   = (const float*)d_in[6];
    const float* W_skip = (const float*)d_in[7];
    const int* lower_tgt = (const int*)d_in[8];
    const int* lower_src = (const int*)d_in[9];
    const int* upper_tgt = (const int*)d_in[10];
    const int* upper_src = (const int*)d_in[11];
    float* out = (float*)d_out;

    static bool attr_set = false;
    if (!attr_set) {
        cudaFuncSetAttribute(gemm_mma_kernel,
                             cudaFuncAttributeMaxDynamicSharedMemorySize, GEMM_SMEM);
        attr_set = true;
    }

    // 1. zero denominators; transpose W
    zero_kernel<<<(2 * NN * 4 + 255) / 256, 256>>>();
    prep_b_kernel<<<(3 * 16384 + 255) / 256, 256>>>(W_low, W_up, W_skip);

    // 2. mma.sync 3xTF32 triple GEMM (branch 2 writes skip*EPS into out)
    dim3 ggrid((NN + 127) / 128, 3);
    gemm_mma_kernel<<<ggrid, 256, GEMM_SMEM>>>(x, out);

    // 3. per-node logit parts
    s_kernel<<<(2 * NN * 4 + 255) / 256, 256>>>(a_sl, a_dl, a_su, a_du);

    // 4. edge softmax numerators + denominators
    pass1_kernel<<<(2 * EE + 255) / 256, 256>>>(lower_tgt, lower_src, upper_tgt, upper_src);

    // 5. weighted aggregation (warp per edge, vector REDs)
    {
        long long threads = (long long)2 * EE * 32;
        int blocks = (int)((threads + 255) / 256);
        pass2_kernel<<<blocks, 256>>>(lower_tgt, lower_src, upper_tgt, upper_src, out);
    }

    // 6. final relu (vectorized)
    relu_kernel<<<(NN * 32 + 255) / 256, 256>>>(out);
}

// round 5
// speedup vs baseline: 1.6740x; 1.2226x over previous
#include <cuda_runtime.h>
#include <cstdint>

#define NN 50000
#define EE 400000
#define EPS_SKIP_F 1.000001f

// ---------------- scratch ----------------
__device__ float g_xm[2][NN * 128];   // per-branch transformed features
__device__ float g_ssrc[2][NN * 4];
__device__ float g_sdst[2][NN * 4];
__device__ float g_denom[2][NN * 4];
__device__ float g_ebuf[2][EE * 4];
__device__ float g_Wt[3][128 * 128];  // W^T as [n][k], fp32

// ---------------- helpers ----------------
__device__ __forceinline__ void split_tf32(float v, uint32_t& hi, uint32_t& lo) {
    uint32_t h;
    asm("cvt.rna.tf32.f32 %0, %1;" : "=r"(h) : "f"(v));
    float r = v - __uint_as_float(h);
    uint32_t l;
    asm("cvt.rna.tf32.f32 %0, %1;" : "=r"(l) : "f"(r));
    hi = h; lo = l;
}

__device__ __forceinline__ void mma_tf32(float* d,
                                         uint32_t a0, uint32_t a1, uint32_t a2, uint32_t a3,
                                         uint32_t b0, uint32_t b1) {
    asm volatile(
        "mma.sync.aligned.m16n8k8.row.col.f32.tf32.tf32.f32 "
        "{%0,%1,%2,%3}, {%4,%5,%6,%7}, {%8,%9}, {%0,%1,%2,%3};"
        : "+f"(d[0]), "+f"(d[1]), "+f"(d[2]), "+f"(d[3])
        : "r"(a0), "r"(a1), "r"(a2), "r"(a3), "r"(b0), "r"(b1));
}

// ---------------- prep: W -> W^T [n][k] ----------------
__global__ void prep_b_kernel(const float* __restrict__ Wl,
                              const float* __restrict__ Wu,
                              const float* __restrict__ Ws) {
    int i = blockIdx.x * blockDim.x + threadIdx.x;
    if (i >= 3 * 16384) return;
    const int b = i / 16384;
    const int r = i & 16383;
    const int k = r >> 7, n = r & 127;
    const float* __restrict__ W = (b == 0) ? Wl : ((b == 1) ? Wu : Ws);
    g_Wt[b][n * 128 + k] = W[k * 128 + n];
}

// ---------------- mma.sync 3xTF32 GEMM + fused logit epilogue ----------------
#define PADK 132
#define GEMM_SMEM (2 * 128 * PADK * 4)

__global__ __launch_bounds__(256, 1) void gemm_mma_kernel(
    const float* __restrict__ x, float* __restrict__ out_skip,
    const float* __restrict__ a_sl, const float* __restrict__ a_dl,
    const float* __restrict__ a_su, const float* __restrict__ a_du)
{
    extern __shared__ float smem[];
    float* As = smem;                  // A[row][k], stride PADK
    float* Bs = smem + 128 * PADK;     // B[n][k],  stride PADK

    const int by = blockIdx.y;
    float* __restrict__ out = (by == 0) ? g_xm[0] : ((by == 1) ? g_xm[1] : out_skip);
    const int bm0 = blockIdx.x * 128;

    const int t = threadIdx.x;
    const int wid = t >> 5, lane = t & 31;
    const int lg = lane >> 2;          // group id 0..7
    const int lt = lane & 3;           // thread-in-group 0..3

    // ---- load A tile ----
#pragma unroll
    for (int i = t; i < 4096; i += 256) {
        const int row = i >> 5;
        const int c4 = i & 31;
        const int m = bm0 + row;
        float4 v = make_float4(0.f, 0.f, 0.f, 0.f);
        if (m < NN) v = *(const float4*)&x[m * 128 + c4 * 4];
        *(float4*)&As[row * PADK + c4 * 4] = v;
    }
    // ---- load B tile ----
    {
        const float* __restrict__ src = g_Wt[by];
#pragma unroll
        for (int i = t; i < 4096; i += 256) {
            const int n = i >> 5;
            const int c4 = i & 31;
            float4 v = *(const float4*)&src[n * 128 + c4 * 4];
            *(float4*)&Bs[n * PADK + c4 * 4] = v;
        }
    }
    __syncthreads();

    // warp tile: 32 rows x 64 cols
    const int wm = (wid & 3) * 32;
    const int wn = (wid >> 2) * 64;

    float acc[2][8][4];
#pragma unroll
    for (int mt = 0; mt < 2; mt++)
#pragma unroll
        for (int nt = 0; nt < 8; nt++)
#pragma unroll
            for (int c = 0; c < 4; c++) acc[mt][nt][c] = 0.f;

#pragma unroll
    for (int k0 = 0; k0 < 128; k0 += 8) {
        uint32_t ah[2][4], al[2][4];
#pragma unroll
        for (int mt = 0; mt < 2; mt++) {
            const int rb = wm + mt * 16 + lg;
            const float v0 = As[rb * PADK + k0 + lt];
            const float v1 = As[(rb + 8) * PADK + k0 + lt];
            const float v2 = As[rb * PADK + k0 + lt + 4];
            const float v3 = As[(rb + 8) * PADK + k0 + lt + 4];
            split_tf32(v0, ah[mt][0], al[mt][0]);
            split_tf32(v1, ah[mt][1], al[mt][1]);
            split_tf32(v2, ah[mt][2], al[mt][2]);
            split_tf32(v3, ah[mt][3], al[mt][3]);
        }
        uint32_t bh[8][2], bl[8][2];
#pragma unroll
        for (int nt = 0; nt < 8; nt++) {
            const int n = wn + nt * 8 + lg;
            const float v0 = Bs[n * PADK + k0 + lt];
            const float v1 = Bs[n * PADK + k0 + lt + 4];
            split_tf32(v0, bh[nt][0], bl[nt][0]);
            split_tf32(v1, bh[nt][1], bl[nt][1]);
        }
#pragma unroll
        for (int mt = 0; mt < 2; mt++)
#pragma unroll
            for (int nt = 0; nt < 8; nt++) {
                mma_tf32(acc[mt][nt], ah[mt][0], ah[mt][1], ah[mt][2], ah[mt][3],
                         bh[nt][0], bh[nt][1]);
                mma_tf32(acc[mt][nt], ah[mt][0], ah[mt][1], ah[mt][2], ah[mt][3],
                         bl[nt][0], bl[nt][1]);
                mma_tf32(acc[mt][nt], al[mt][0], al[mt][1], al[mt][2], al[mt][3],
                         bh[nt][0], bh[nt][1]);
            }
    }

    // ---- epilogue: store xm (or skip*EPS) ----
    const float scale = (by == 2) ? EPS_SKIP_F : 1.0f;
#pragma unroll
    for (int mt = 0; mt < 2; mt++) {
        const int r0 = wm + mt * 16 + lg;
        const int m0 = bm0 + r0;
        const int m1 = m0 + 8;
#pragma unroll
        for (int nt = 0; nt < 8; nt++) {
            const int col = wn + nt * 8 + 2 * lt;
            if (m0 < NN) {
                float2 v = make_float2(acc[mt][nt][0] * scale, acc[mt][nt][1] * scale);
                *(float2*)&out[m0 * 128 + col] = v;
            }
            if (m1 < NN) {
                float2 v = make_float2(acc[mt][nt][2] * scale, acc[mt][nt][3] * scale);
                *(float2*)&out[m1 * 128 + col] = v;
            }
        }
    }

    // ---- fused attention-logit epilogue (branches 0,1 only) ----
    // Warp's 64 cols = heads h0, h0+1. Per thread: 4 rows x 2 heads partial
    // dots over its 8 cols per head, then 2-level shfl.xor over lt completes.
    if (by < 2) {
        const float* __restrict__ asrc = (by == 0) ? a_sl : a_su;
        const float* __restrict__ adst = (by == 0) ? a_dl : a_du;
        const int h0 = wn >> 5;   // 0 or 2

        float ssum[2][4], dsum[2][4];   // [head][row: mt0/m0, mt0/m1, mt1/m0, mt1/m1]
#pragma unroll
        for (int hh = 0; hh < 2; hh++)
#pragma unroll
            for (int rr = 0; rr < 4; rr++) { ssum[hh][rr] = 0.f; dsum[hh][rr] = 0.f; }

#pragma unroll
        for (int hh = 0; hh < 2; hh++) {
#pragma unroll
            for (int nt4 = 0; nt4 < 4; nt4++) {
                const int nt = hh * 4 + nt4;
                const int ai = (h0 + hh) * 32 + nt4 * 8 + 2 * lt;
                const float s0 = asrc[ai], s1 = asrc[ai + 1];
                const float d0 = adst[ai], d1 = adst[ai + 1];
#pragma unroll
                for (int mt = 0; mt < 2; mt++) {
                    ssum[hh][mt * 2 + 0] += acc[mt][nt][0] * s0 + acc[mt][nt][1] * s1;
                    ssum[hh][mt * 2 + 1] += acc[mt][nt][2] * s0 + acc[mt][nt][3] * s1;
                    dsum[hh][mt * 2 + 0] += acc[mt][nt][0] * d0 + acc[mt][nt][1] * d1;
                    dsum[hh][mt * 2 + 1] += acc[mt][nt][2] * d0 + acc[mt][nt][3] * d1;
                }
            }
        }
#pragma unroll
        for (int d = 1; d <= 2; d <<= 1) {
#pragma unroll
            for (int hh = 0; hh < 2; hh++)
#pragma unroll
                for (int rr = 0; rr < 4; rr++) {
                    ssum[hh][rr] += __shfl_xor_sync(0xFFFFFFFF, ssum[hh][rr], d);
                    dsum[hh][rr] += __shfl_xor_sync(0xFFFFFFFF, dsum[hh][rr], d);
                }
        }
        if (lt == 0) {
#pragma unroll
            for (int rr = 0; rr < 4; rr++) {
                const int row = bm0 + wm + ((rr & 1) ? 8 : 0) + ((rr >> 1) ? 16 : 0) + lg;
                if (row < NN) {
#pragma unroll
                    for (int hh = 0; hh < 2; hh++) {
                        g_ssrc[by][row * 4 + h0 + hh] = ssum[hh][rr];
                        g_sdst[by][row * 4 + h0 + hh] = dsum[hh][rr];
                    }
                }
            }
        }
    }
}

// ---------------- attention pipeline ----------------
__global__ void zero_kernel() {
    int i = blockIdx.x * blockDim.x + threadIdx.x;
    if (i < 2 * NN * 4) ((float*)g_denom)[i] = 0.0f;
}

__device__ __forceinline__ float lrelu_exp(float a) {
    a = (a > 0.f) ? a : 0.01f * a;
    return __expf(a);
}

__global__ void pass1_kernel(const int* __restrict__ t0, const int* __restrict__ s0,
                             const int* __restrict__ t1, const int* __restrict__ s1)
{
    int idx = blockIdx.x * blockDim.x + threadIdx.x;
    if (idx >= 2 * EE) return;
    const int branch = (idx >= EE) ? 1 : 0;
    const int e = idx - branch * EE;
    const int tgt = (branch ? t1 : t0)[e];
    const int src = (branch ? s1 : s0)[e];
    float4 ss = *(const float4*)&g_ssrc[branch][src * 4];
    float4 sd = *(const float4*)&g_sdst[branch][tgt * 4];
    float ex = lrelu_exp(ss.x + sd.x);
    float ey = lrelu_exp(ss.y + sd.y);
    float ez = lrelu_exp(ss.z + sd.z);
    float ew = lrelu_exp(ss.w + sd.w);
    *(float4*)&g_ebuf[branch][e * 4] = make_float4(ex, ey, ez, ew);
    float* p = &g_denom[branch][tgt * 4];
    asm volatile("red.global.add.v4.f32 [%0], {%1,%2,%3,%4};"
                 :: "l"(p), "f"(ex), "f"(ey), "f"(ez), "f"(ew) : "memory");
}

__global__ void pass2_kernel(const int* __restrict__ t0, const int* __restrict__ s0,
                             const int* __restrict__ t1, const int* __restrict__ s1,
                             float* __restrict__ out)
{
    const int gw = (blockIdx.x * blockDim.x + threadIdx.x) >> 5;
    if (gw >= 2 * EE) return;
    const int lane = threadIdx.x & 31;
    const int branch = (gw >= EE) ? 1 : 0;
    const int e = gw - branch * EE;
    const int tgt = (branch ? t1 : t0)[e];
    const int src = (branch ? s1 : s0)[e];
    const int h = lane >> 3;
    const float eh = g_ebuf[branch][e * 4 + h];
    const float dh = g_denom[branch][tgt * 4 + h];
    const float w = eh / (dh + 1e-16f);
    const float4 v = *(const float4*)&g_xm[branch][src * 128 + lane * 4];
    float* p = &out[tgt * 128 + lane * 4];
    asm volatile("red.global.add.v4.f32 [%0], {%1,%2,%3,%4};"
                 :: "l"(p), "f"(v.x * w), "f"(v.y * w), "f"(v.z * w), "f"(v.w * w)
                 : "memory");
}

__global__ void relu_kernel(float* __restrict__ out) {
    int i = blockIdx.x * blockDim.x + threadIdx.x;
    if (i < NN * 32) {
        float4* p = (float4*)out + i;
        float4 v = *p;
        v.x = fmaxf(v.x, 0.f); v.y = fmaxf(v.y, 0.f);
        v.z = fmaxf(v.z, 0.f); v.w = fmaxf(v.w, 0.f);
        *p = v;
    }
}

// ---------------- launch ----------------
extern "C" void kernel_launch(void* const* d_in, const int* in_sizes, int n_in,
                              void* d_out, int out_size)
{
    const float* x      = (const float*)d_in[0];
    const float* W_low  = (const float*)d_in[1];
    const float* a_sl   = (const float*)d_in[2];
    const float* a_dl   = (const float*)d_in[3];
    const float* W_up   = (const float*)d_in[4];
    const float* a_su   = (const float*)d_in[5];
    const float* a_du   = (const float*)d_in[6];
    const float* W_skip = (const float*)d_in[7];
    const int* lower_tgt = (const int*)d_in[8];
    const int* lower_src = (const int*)d_in[9];
    const int* upper_tgt = (const int*)d_in[10];
    const int* upper_src = (const int*)d_in[11];
    float* out = (float*)d_out;

    static bool attr_set = false;
    if (!attr_set) {
        cudaFuncSetAttribute(gemm_mma_kernel,
                             cudaFuncAttributeMaxDynamicSharedMemorySize, GEMM_SMEM);
        attr_set = true;
    }

    // 1. zero denominators; transpose W
    zero_kernel<<<(2 * NN * 4 + 255) / 256, 256>>>();
    prep_b_kernel<<<(3 * 16384 + 255) / 256, 256>>>(W_low, W_up, W_skip);

    // 2. triple GEMM + fused logit epilogue (branch 2 writes skip*EPS into out)
    dim3 ggrid((NN + 127) / 128, 3);
    gemm_mma_kernel<<<ggrid, 256, GEMM_SMEM>>>(x, out, a_sl, a_dl, a_su, a_du);

    // 3. edge softmax numerators + denominators
    pass1_kernel<<<(2 * EE + 255) / 256, 256>>>(lower_tgt, lower_src, upper_tgt, upper_src);

    // 4. weighted aggregation (warp per edge, vector REDs)
    {
        long long threads = (long long)2 * EE * 32;
        int blocks = (int)((threads + 255) / 256);
        pass2_kernel<<<blocks, 256>>>(lower_tgt, lower_src, upper_tgt, upper_src, out);
    }

    // 5. final relu (vectorized)
    relu_kernel<<<(NN * 32 + 255) / 256, 256>>>(out);
}

// round 6
// speedup vs baseline: 2.0215x; 1.2076x over previous
#include <cuda_runtime.h>
#include <cuda_bf16.h>
#include <cstdint>

#define NN 50000
#define EE 400000
#define EPS_SKIP_F 1.000001f

// ---------------- scratch ----------------
__device__ float    g_xm[2][NN * 128];   // per-branch transformed features
__device__ float    g_ssrc[2][NN * 4];
__device__ float    g_sdst[2][NN * 4];
__device__ float    g_denom[2][NN * 4];
__device__ float    g_ebuf[2][EE * 4];
__device__ uint32_t g_Wtp[3][2][128 * 64];  // W^T split: [branch][hi/lo][n][kpair] bf16x2

// ---------------- helpers ----------------
__device__ __forceinline__ void split_pack(float v0, float v1, uint32_t& hi, uint32_t& lo) {
    __nv_bfloat16 h0 = __float2bfloat16_rn(v0);
    __nv_bfloat16 h1 = __float2bfloat16_rn(v1);
    float r0 = v0 - __bfloat162float(h0);
    float r1 = v1 - __bfloat162float(h1);
    __nv_bfloat162 hp; hp.x = h0; hp.y = h1;
    __nv_bfloat162 lp; lp.x = __float2bfloat16_rn(r0); lp.y = __float2bfloat16_rn(r1);
    hi = *(uint32_t*)&hp;
    lo = *(uint32_t*)&lp;
}

__device__ __forceinline__ void mma_bf16(float* d,
                                         uint32_t a0, uint32_t a1, uint32_t a2, uint32_t a3,
                                         uint32_t b0, uint32_t b1) {
    asm volatile(
        "mma.sync.aligned.m16n8k16.row.col.f32.bf16.bf16.f32 "
        "{%0,%1,%2,%3}, {%4,%5,%6,%7}, {%8,%9}, {%0,%1,%2,%3};"
        : "+f"(d[0]), "+f"(d[1]), "+f"(d[2]), "+f"(d[3])
        : "r"(a0), "r"(a1), "r"(a2), "r"(a3), "r"(b0), "r"(b1));
}

// ---------------- prep: W -> W^T, split to bf16 hi/lo, pack k-pairs ----------------
__global__ void prep_b_kernel(const float* __restrict__ Wl,
                              const float* __restrict__ Wu,
                              const float* __restrict__ Ws) {
    int i = blockIdx.x * blockDim.x + threadIdx.x;
    if (i >= 3 * 8192) return;
    const int b = i / 8192;
    const int r = i & 8191;
    const int n = r >> 6, kp = r & 63;
    const float* __restrict__ W = (b == 0) ? Wl : ((b == 1) ? Wu : Ws);
    const float v0 = W[(2 * kp) * 128 + n];
    const float v1 = W[(2 * kp + 1) * 128 + n];
    uint32_t hi, lo;
    split_pack(v0, v1, hi, lo);
    g_Wtp[b][0][n * 64 + kp] = hi;
    g_Wtp[b][1][n * 64 + kp] = lo;
}

// ---------------- bf16x3 mma GEMM + fused logit epilogue ----------------
#define PADP 68                       // kpair stride (words): bank = (4*lg+lt)%32, conflict-free
#define TSZ (128 * PADP)              // words per tile array
#define GEMM_SMEM (4 * TSZ * 4)       // Ah, Al, Bh, Bl

__global__ __launch_bounds__(256, 1) void gemm_mma_kernel(
    const float* __restrict__ x, float* __restrict__ out_skip,
    const float* __restrict__ a_sl, const float* __restrict__ a_dl,
    const float* __restrict__ a_su, const float* __restrict__ a_du)
{
    extern __shared__ uint32_t smem[];
    uint32_t* Ah = smem;
    uint32_t* Al = smem + TSZ;
    uint32_t* Bh = smem + 2 * TSZ;
    uint32_t* Bl = smem + 3 * TSZ;

    const int by = blockIdx.y;
    float* __restrict__ out = (by == 0) ? g_xm[0] : ((by == 1) ? g_xm[1] : out_skip);
    const int bm0 = blockIdx.x * 128;

    const int t = threadIdx.x;
    const int wid = t >> 5, lane = t & 31;
    const int lg = lane >> 2;          // 0..7
    const int lt = lane & 3;           // 0..3

    // ---- load + split A tile (x rows fp32 -> bf16 hi/lo kpairs) ----
#pragma unroll
    for (int i = t; i < 4096; i += 256) {
        const int row = i >> 5;
        const int c4 = i & 31;         // float4 index; covers kpairs 2c4, 2c4+1
        const int m = bm0 + row;
        float4 v = make_float4(0.f, 0.f, 0.f, 0.f);
        if (m < NN) v = *(const float4*)&x[m * 128 + c4 * 4];
        uint32_t h0, l0, h1, l1;
        split_pack(v.x, v.y, h0, l0);
        split_pack(v.z, v.w, h1, l1);
        const int base = row * PADP + 2 * c4;
        Ah[base] = h0; Ah[base + 1] = h1;
        Al[base] = l0; Al[base + 1] = l1;
    }
    // ---- load B tile (pre-split hi/lo images) ----
    {
        const uint32_t* __restrict__ sh = g_Wtp[by][0];
        const uint32_t* __restrict__ sl = g_Wtp[by][1];
#pragma unroll
        for (int i = t; i < 2048; i += 256) {
            const int n = i >> 4;
            const int p4 = i & 15;     // uint4 over 64 kpairs
            uint4 vh = *(const uint4*)&sh[n * 64 + p4 * 4];
            uint4 vl = *(const uint4*)&sl[n * 64 + p4 * 4];
            const int base = n * PADP + p4 * 4;
            *(uint4*)&Bh[base] = vh;
            *(uint4*)&Bl[base] = vl;
        }
    }
    __syncthreads();

    // warp tile: 32 rows x 64 cols
    const int wm = (wid & 3) * 32;
    const int wn = (wid >> 2) * 64;

    float acc[2][8][4];
#pragma unroll
    for (int mt = 0; mt < 2; mt++)
#pragma unroll
        for (int nt = 0; nt < 8; nt++)
#pragma unroll
            for (int c = 0; c < 4; c++) acc[mt][nt][c] = 0.f;

#pragma unroll
    for (int ks = 0; ks < 8; ks++) {
        const int kp = ks * 8;         // kpair base for this k16 step
        uint32_t ah[2][4], al[2][4];
#pragma unroll
        for (int mt = 0; mt < 2; mt++) {
            const int rb = wm + mt * 16 + lg;
            const int i0 = rb * PADP + kp + lt;
            const int i1 = (rb + 8) * PADP + kp + lt;
            ah[mt][0] = Ah[i0];     al[mt][0] = Al[i0];
            ah[mt][1] = Ah[i1];     al[mt][1] = Al[i1];
            ah[mt][2] = Ah[i0 + 4]; al[mt][2] = Al[i0 + 4];
            ah[mt][3] = Ah[i1 + 4]; al[mt][3] = Al[i1 + 4];
        }
        uint32_t bh[8][2], bl[8][2];
#pragma unroll
        for (int nt = 0; nt < 8; nt++) {
            const int n = wn + nt * 8 + lg;
            const int i0 = n * PADP + kp + lt;
            bh[nt][0] = Bh[i0];     bl[nt][0] = Bl[i0];
            bh[nt][1] = Bh[i0 + 4]; bl[nt][1] = Bl[i0 + 4];
        }
#pragma unroll
        for (int mt = 0; mt < 2; mt++)
#pragma unroll
            for (int nt = 0; nt < 8; nt++) {
                mma_bf16(acc[mt][nt], ah[mt][0], ah[mt][1], ah[mt][2], ah[mt][3],
                         bl[nt][0], bl[nt][1]);
                mma_bf16(acc[mt][nt], al[mt][0], al[mt][1], al[mt][2], al[mt][3],
                         bh[nt][0], bh[nt][1]);
                mma_bf16(acc[mt][nt], ah[mt][0], ah[mt][1], ah[mt][2], ah[mt][3],
                         bh[nt][0], bh[nt][1]);
            }
    }

    // ---- epilogue: store xm (or skip*EPS) ----
    const float scale = (by == 2) ? EPS_SKIP_F : 1.0f;
#pragma unroll
    for (int mt = 0; mt < 2; mt++) {
        const int r0 = wm + mt * 16 + lg;
        const int m0 = bm0 + r0;
        const int m1 = m0 + 8;
#pragma unroll
        for (int nt = 0; nt < 8; nt++) {
            const int col = wn + nt * 8 + 2 * lt;
            if (m0 < NN) {
                float2 v = make_float2(acc[mt][nt][0] * scale, acc[mt][nt][1] * scale);
                *(float2*)&out[m0 * 128 + col] = v;
            }
            if (m1 < NN) {
                float2 v = make_float2(acc[mt][nt][2] * scale, acc[mt][nt][3] * scale);
                *(float2*)&out[m1 * 128 + col] = v;
            }
        }
    }

    // ---- fused attention-logit epilogue (branches 0,1 only) ----
    if (by < 2) {
        const float* __restrict__ asrc = (by == 0) ? a_sl : a_su;
        const float* __restrict__ adst = (by == 0) ? a_dl : a_du;
        const int h0 = wn >> 5;   // 0 or 2

        float ssum[2][4], dsum[2][4];
#pragma unroll
        for (int hh = 0; hh < 2; hh++)
#pragma unroll
            for (int rr = 0; rr < 4; rr++) { ssum[hh][rr] = 0.f; dsum[hh][rr] = 0.f; }

#pragma unroll
        for (int hh = 0; hh < 2; hh++) {
#pragma unroll
            for (int nt4 = 0; nt4 < 4; nt4++) {
                const int nt = hh * 4 + nt4;
                const int ai = (h0 + hh) * 32 + nt4 * 8 + 2 * lt;
                const float s0 = asrc[ai], s1 = asrc[ai + 1];
                const float d0 = adst[ai], d1 = adst[ai + 1];
#pragma unroll
                for (int mt = 0; mt < 2; mt++) {
                    ssum[hh][mt * 2 + 0] += acc[mt][nt][0] * s0 + acc[mt][nt][1] * s1;
                    ssum[hh][mt * 2 + 1] += acc[mt][nt][2] * s0 + acc[mt][nt][3] * s1;
                    dsum[hh][mt * 2 + 0] += acc[mt][nt][0] * d0 + acc[mt][nt][1] * d1;
                    dsum[hh][mt * 2 + 1] += acc[mt][nt][2] * d0 + acc[mt][nt][3] * d1;
                }
            }
        }
#pragma unroll
        for (int d = 1; d <= 2; d <<= 1) {
#pragma unroll
            for (int hh = 0; hh < 2; hh++)
#pragma unroll
                for (int rr = 0; rr < 4; rr++) {
                    ssum[hh][rr] += __shfl_xor_sync(0xFFFFFFFF, ssum[hh][rr], d);
                    dsum[hh][rr] += __shfl_xor_sync(0xFFFFFFFF, dsum[hh][rr], d);
                }
        }
        if (lt == 0) {
#pragma unroll
            for (int rr = 0; rr < 4; rr++) {
                const int row = bm0 + wm + ((rr & 1) ? 8 : 0) + ((rr >> 1) ? 16 : 0) + lg;
                if (row < NN) {
#pragma unroll
                    for (int hh = 0; hh < 2; hh++) {
                        g_ssrc[by][row * 4 + h0 + hh] = ssum[hh][rr];
                        g_sdst[by][row * 4 + h0 + hh] = dsum[hh][rr];
                    }
                }
            }
        }
    }
}

// ---------------- attention pipeline ----------------
__global__ void zero_kernel() {
    int i = blockIdx.x * blockDim.x + threadIdx.x;
    if (i < 2 * NN * 4) ((float*)g_denom)[i] = 0.0f;
}

__device__ __forceinline__ float lrelu_exp(float a) {
    a = (a > 0.f) ? a : 0.01f * a;
    return __expf(a);
}

__global__ void pass1_kernel(const int* __restrict__ t0, const int* __restrict__ s0,
                             const int* __restrict__ t1, const int* __restrict__ s1)
{
    int idx = blockIdx.x * blockDim.x + threadIdx.x;
    if (idx >= 2 * EE) return;
    const int branch = (idx >= EE) ? 1 : 0;
    const int e = idx - branch * EE;
    const int tgt = (branch ? t1 : t0)[e];
    const int src = (branch ? s1 : s0)[e];
    float4 ss = *(const float4*)&g_ssrc[branch][src * 4];
    float4 sd = *(const float4*)&g_sdst[branch][tgt * 4];
    float ex = lrelu_exp(ss.x + sd.x);
    float ey = lrelu_exp(ss.y + sd.y);
    float ez = lrelu_exp(ss.z + sd.z);
    float ew = lrelu_exp(ss.w + sd.w);
    *(float4*)&g_ebuf[branch][e * 4] = make_float4(ex, ey, ez, ew);
    float* p = &g_denom[branch][tgt * 4];
    asm volatile("red.global.add.v4.f32 [%0], {%1,%2,%3,%4};"
                 :: "l"(p), "f"(ex), "f"(ey), "f"(ez), "f"(ew) : "memory");
}

__global__ void pass2_kernel(const int* __restrict__ t0, const int* __restrict__ s0,
                             const int* __restrict__ t1, const int* __restrict__ s1,
                             float* __restrict__ out)
{
    const int gw = (blockIdx.x * blockDim.x + threadIdx.x) >> 5;
    if (gw >= 2 * EE) return;
    const int lane = threadIdx.x & 31;
    const int branch = (gw >= EE) ? 1 : 0;
    const int e = gw - branch * EE;
    const int tgt = (branch ? t1 : t0)[e];
    const int src = (branch ? s1 : s0)[e];
    const int h = lane >> 3;
    const float eh = g_ebuf[branch][e * 4 + h];
    const float dh = g_denom[branch][tgt * 4 + h];
    const float w = eh / (dh + 1e-16f);
    const float4 v = *(const float4*)&g_xm[branch][src * 128 + lane * 4];
    float* p = &out[tgt * 128 + lane * 4];
    asm volatile("red.global.add.v4.f32 [%0], {%1,%2,%3,%4};"
                 :: "l"(p), "f"(v.x * w), "f"(v.y * w), "f"(v.z * w), "f"(v.w * w)
                 : "memory");
}

__global__ void relu_kernel(float* __restrict__ out) {
    int i = blockIdx.x * blockDim.x + threadIdx.x;
    if (i < NN * 32) {
        float4* p = (float4*)out + i;
        float4 v = *p;
        v.x = fmaxf(v.x, 0.f); v.y = fmaxf(v.y, 0.f);
        v.z = fmaxf(v.z, 0.f); v.w = fmaxf(v.w, 0.f);
        *p = v;
    }
}

// ---------------- launch ----------------
extern "C" void kernel_launch(void* const* d_in, const int* in_sizes, int n_in,
                              void* d_out, int out_size)
{
    const float* x      = (const float*)d_in[0];
    const float* W_low  = (const float*)d_in[1];
    const float* a_sl   = (const float*)d_in[2];
    const float* a_dl   = (const float*)d_in[3];
    const float* W_up   = (const float*)d_in[4];
    const float* a_su   = (const float*)d_in[5];
    const float* a_du   = (const float*)d_in[6];
    const float* W_skip = (const float*)d_in[7];
    const int* lower_tgt = (const int*)d_in[8];
    const int* lower_src = (const int*)d_in[9];
    const int* upper_tgt = (const int*)d_in[10];
    const int* upper_src = (const int*)d_in[11];
    float* out = (float*)d_out;

    static bool attr_set = false;
    if (!attr_set) {
        cudaFuncSetAttribute(gemm_mma_kernel,
                             cudaFuncAttributeMaxDynamicSharedMemorySize, GEMM_SMEM);
        attr_set = true;
    }

    // 1. zero denominators; split/transpose W
    zero_kernel<<<(2 * NN * 4 + 255) / 256, 256>>>();
    prep_b_kernel<<<(3 * 8192 + 255) / 256, 256>>>(W_low, W_up, W_skip);

    // 2. bf16x3 triple GEMM + fused logit epilogue (branch 2 writes skip*EPS into out)
    dim3 ggrid((NN + 127) / 128, 3);
    gemm_mma_kernel<<<ggrid, 256, GEMM_SMEM>>>(x, out, a_sl, a_dl, a_su, a_du);

    // 3. edge softmax numerators + denominators
    pass1_kernel<<<(2 * EE + 255) / 256, 256>>>(lower_tgt, lower_src, upper_tgt, upper_src);

    // 4. weighted aggregation (warp per edge, vector REDs)
    {
        long long threads = (long long)2 * EE * 32;
        int blocks = (int)((threads + 255) / 256);
        pass2_kernel<<<blocks, 256>>>(lower_tgt, lower_src, upper_tgt, upper_src, out);
    }

    // 5. final relu (vectorized)
    relu_kernel<<<(NN * 32 + 255) / 256, 256>>>(out);
}